// round 7
// baseline (speedup 1.0000x reference)
#include <cuda_runtime.h>
#include <math.h>

#define IMG_W 1024
#define IMG_H 1024
#define IMG_B 8
#define IMG_HW (IMG_H * IMG_W)

#define TX 32
#define TY 16
#define NTHR (TX * TY)

// Regions per tile (origin offsets relative to output tile origin):
//   img    : 40 x 24  (offset -4,-4)
//   smooth : 36 x 20  (offset -2,-2)
//   g2/bin : 34 x 18  (offset -1,-1)

// ---------------------------------------------------------------------------
// Scratch (allocation-free rule: __device__ globals)
// ---------------------------------------------------------------------------
__device__ float g_sup[(size_t)IMG_B * IMG_HW];
__device__ float g_strong[(size_t)IMG_B * IMG_HW];
__device__ unsigned int g_min_bits;
__device__ unsigned int g_max_bits;

__device__ __forceinline__ int refl(int i, int n) {
    if (i < 0) i = -i;
    if (i >= n) i = 2 * n - 2 - i;
    return i;
}

__device__ __forceinline__ float sigm(float x) {
    return 1.0f / (1.0f + expf(-x));
}

// ---------------------------------------------------------------------------
// Fused kernel: image -> gaussian(fp64) -> sobel(fp64) -> NMS -> sup (+min/max)
// ---------------------------------------------------------------------------
__global__ __launch_bounds__(NTHR) void fused_front_kernel(const float* __restrict__ img) {
    __shared__ double s_img[24][40];
    __shared__ double s_sm[20][36];
    __shared__ double s_g2[18][34];
    __shared__ unsigned char s_bin[18][34];
    __shared__ float smin[NTHR / 32], smax[NTHR / 32];

    const int x0 = blockIdx.x * TX;
    const int y0 = blockIdx.y * TY;
    const int b  = blockIdx.z;
    const float* p = img + (size_t)b * IMG_HW;
    const int tid = threadIdx.x;

    // ---- Stage 1: load image region (reflect handled ONCE here) ----
    for (int i = tid; i < 24 * 40; i += NTHR) {
        const int yy = i / 40, xx = i - yy * 40;
        const int gx = refl(x0 - 4 + xx, IMG_W);
        const int gy = refl(y0 - 4 + yy, IMG_H);
        s_img[yy][xx] = (double)p[gy * IMG_W + gx];
    }
    __syncthreads();

    // ---- Stage 2: 5x5 Gaussian, fp64 accumulation, exact fp32 2D weights ----
    {
        const float w5[5] = {0.054488684549640294f, 0.24420134200323337f,
                             0.4026199468935272f,  0.24420134200323337f,
                             0.054488684549640294f};
        for (int i = tid; i < 20 * 36; i += NTHR) {
            const int sy = i / 36, sx = i - sy * 36;
            double acc = 0.0;
#pragma unroll
            for (int ky = 0; ky < 5; ky++) {
#pragma unroll
                for (int kx = 0; kx < 5; kx++) {
                    // fp32 product = reference's fp32 outer-product weight, exact
                    const double w = (double)(w5[ky] * w5[kx]);
                    acc = fma(w, s_img[sy + ky][sx + kx], acc);
                }
            }
            s_sm[sy][sx] = acc;
        }
    }
    __syncthreads();

    // ---- Stage 3: Sobel -> grad^2 + direction bin (fp64) ----
    for (int i = tid; i < 18 * 34; i += NTHR) {
        const int jy = i / 34, jx = i - jy * 34;
        const double v00 = s_sm[jy + 0][jx + 0], v01 = s_sm[jy + 0][jx + 1], v02 = s_sm[jy + 0][jx + 2];
        const double v10 = s_sm[jy + 1][jx + 0],                              v12 = s_sm[jy + 1][jx + 2];
        const double v20 = s_sm[jy + 2][jx + 0], v21 = s_sm[jy + 2][jx + 1], v22 = s_sm[jy + 2][jx + 2];

        const double gx = (v02 - v00) + 2.0 * (v12 - v10) + (v22 - v20);
        const double gy = (v00 + 2.0 * v01 + v02) - (v20 + 2.0 * v21 + v22);
        const double g2 = fma(gx, gx, gy * gy);

        // direction bins via exact ratio tests (== atan2-degree bins):
        //   0: [0,22.5) U [157.5,180) -> E/W     1: [22.5,67.5)  -> SW/NE
        //   2: [67.5,112.5)           -> N/S     3: [112.5,157.5)-> SE/NW
        const double ax = fabs(gx), ay = fabs(gy);
        unsigned char bin;
        if (ay < 0.41421356237309503 * ax)       bin = 0;
        else if (ay >= 2.414213562373095 * ax)   bin = 2;
        else                                     bin = ((gx > 0.0) == (gy > 0.0)) ? 1 : 3;

        s_g2[jy][jx]  = g2;
        s_bin[jy][jx] = bin;
    }
    __syncthreads();

    // ---- Stage 4: NMS (exact compares on grad^2) + fused min/max reduce ----
    const int tx = tid & (TX - 1);
    const int ty = tid / TX;

    float sup = 0.0f;
    {
        const double c   = s_g2[ty + 1][tx + 1];
        const int    bin = s_bin[ty + 1][tx + 1];
        double na, nb;
        if (bin == 0)      { na = s_g2[ty + 1][tx + 2]; nb = s_g2[ty + 1][tx + 0]; } // E,W
        else if (bin == 2) { na = s_g2[ty + 0][tx + 1]; nb = s_g2[ty + 2][tx + 1]; } // N,S
        else if (bin == 1) { na = s_g2[ty + 2][tx + 0]; nb = s_g2[ty + 0][tx + 2]; } // SW,NE
        else               { na = s_g2[ty + 2][tx + 2]; nb = s_g2[ty + 0][tx + 0]; } // SE,NW

        if (c > na && c > nb) {
            float r = sqrtf((float)c);
            if (c > 1e-38) {  // one Newton step toward sqrt(exact g2)
                const double resid = fma(-(double)r, (double)r, c);
                r = fmaf((float)resid, 0.5f / r, r);
            }
            sup = r;
        }
    }
    g_sup[(size_t)b * IMG_HW + (size_t)(y0 + ty) * IMG_W + (x0 + tx)] = sup;

    // block min/max (sup >= 0 -> uint order == float order)
    float vmin = sup, vmax = sup;
#pragma unroll
    for (int off = 16; off > 0; off >>= 1) {
        vmin = fminf(vmin, __shfl_xor_sync(0xFFFFFFFF, vmin, off));
        vmax = fmaxf(vmax, __shfl_xor_sync(0xFFFFFFFF, vmax, off));
    }
    const int wid = tid >> 5;
    if ((tid & 31) == 0) { smin[wid] = vmin; smax[wid] = vmax; }
    __syncthreads();
    if (tid == 0) {
        float bmin = smin[0], bmax = smax[0];
#pragma unroll
        for (int i = 1; i < NTHR / 32; i++) {
            bmin = fminf(bmin, smin[i]);
            bmax = fmaxf(bmax, smax[i]);
        }
        atomicMin(&g_min_bits, __float_as_uint(bmin));
        atomicMax(&g_max_bits, __float_as_uint(bmax));
    }
}

// ---------------------------------------------------------------------------
// init reduction scalars
// ---------------------------------------------------------------------------
__global__ void init_minmax_kernel() {
    g_min_bits = 0x7F800000u;  // +inf
    g_max_bits = 0u;           // 0.0f (sup >= 0)
}

// ---------------------------------------------------------------------------
// strong = sigmoid(100*(sup - high))
// ---------------------------------------------------------------------------
__global__ __launch_bounds__(256) void strong_kernel() {
    const size_t idx = (size_t)blockIdx.x * 256 + threadIdx.x;
    const float mn = __uint_as_float(g_min_bits);
    const float mx = __uint_as_float(g_max_bits);
    const float high = mn + (mx - mn) * 0.25f;
    g_strong[idx] = sigm(100.0f * (g_sup[idx] - high));
}

// ---------------------------------------------------------------------------
// final mask = strong + weak * sigmoid(100*(has_strong - 0.5))
// ---------------------------------------------------------------------------
__global__ __launch_bounds__(256) void final_kernel(float* __restrict__ out) {
    const int x = blockIdx.x * 32 + threadIdx.x;
    const int y = blockIdx.y * 8 + threadIdx.y;
    const int b = blockIdx.z;
    const float* st = g_strong + (size_t)b * IMG_HW;
    const float* su = g_sup + (size_t)b * IMG_HW;

    const float mn = __uint_as_float(g_min_bits);
    const float mx = __uint_as_float(g_max_bits);
    const float low = mn + (mx - mn) * 0.1f;

    const size_t idx = (size_t)y * IMG_W + x;
    const float s_c = st[idx];
    const float sup = su[idx];
    const float weak = sigm(100.0f * (sup - low)) * (1.0f - s_c);

    float hs = 0.0f;
    if (x >= 1 && x < IMG_W - 1 && y >= 1 && y < IMG_H - 1) {
#pragma unroll
        for (int dy = -1; dy <= 1; dy++)
#pragma unroll
            for (int dx = -1; dx <= 1; dx++)
                hs += st[(y + dy) * IMG_W + (x + dx)];
    } else {
#pragma unroll
        for (int dy = -1; dy <= 1; dy++) {
            const int yy = refl(y + dy, IMG_H);
#pragma unroll
            for (int dx = -1; dx <= 1; dx++)
                hs += st[yy * IMG_W + refl(x + dx, IMG_W)];
        }
    }
    out[(size_t)b * IMG_HW + idx] = s_c + weak * sigm(100.0f * (hs - 0.5f));
}

// ---------------------------------------------------------------------------
extern "C" void kernel_launch(void* const* d_in, const int* in_sizes, int n_in,
                              void* d_out, int out_size) {
    const float* image = (const float*)d_in[0];
    float* out = (float*)d_out;

    init_minmax_kernel<<<1, 1>>>();

    dim3 grdA(IMG_W / TX, IMG_H / TY, IMG_B);
    fused_front_kernel<<<grdA, NTHR>>>(image);

    strong_kernel<<<((size_t)IMG_B * IMG_HW) / 256, 256>>>();

    dim3 blkF(32, 8, 1);
    dim3 grdF(IMG_W / 32, IMG_H / 8, IMG_B);
    final_kernel<<<grdF, blkF>>>(out);
}

// round 8
// speedup vs baseline: 4.9557x; 4.9557x over previous
#include <cuda_runtime.h>
#include <math.h>
#include <stdint.h>

#define IMG_W 1024
#define IMG_H 1024
#define IMG_B 8
#define IMG_HW (IMG_H * IMG_W)

#define TX 32
#define TY 16
#define NTHR 512
#define NPAIR 4   // batch pairs (2p, 2p+1)

// Tile regions (offsets relative to output tile origin):
//   img : 40 x 24  (-4,-4)   row-smoothed : 36 x 24  (-2,-4)
//   sm  : 36 x 20  (-2,-2)   g2/bin       : 34 x 18  (-1,-1)

// ---------------------------------------------------------------------------
// Scratch (allocation-free rule: __device__ globals)
// ---------------------------------------------------------------------------
__device__ float2 g_sup2[(size_t)NPAIR * IMG_HW];  // pair-interleaved sup
__device__ unsigned int g_min_bits;
__device__ unsigned int g_max_bits;

__device__ __forceinline__ int refl(int i, int n) {
    if (i < 0) i = -i;
    if (i >= n) i = 2 * n - 2 - i;
    return i;
}
__device__ __forceinline__ float sigm(float x) { return 1.0f / (1.0f + expf(-x)); }

// ---------------------------------------------------------------------------
// Packed f32x2 primitives (FFMA2 path — PTX only)
// ---------------------------------------------------------------------------
__device__ __forceinline__ uint64_t f2add(uint64_t a, uint64_t b) {
    uint64_t r; asm("add.rn.f32x2 %0, %1, %2;" : "=l"(r) : "l"(a), "l"(b)); return r;
}
__device__ __forceinline__ uint64_t f2mul(uint64_t a, uint64_t b) {
    uint64_t r; asm("mul.rn.f32x2 %0, %1, %2;" : "=l"(r) : "l"(a), "l"(b)); return r;
}
__device__ __forceinline__ uint64_t f2fma(uint64_t a, uint64_t b, uint64_t c) {
    uint64_t r; asm("fma.rn.f32x2 %0, %1, %2, %3;" : "=l"(r) : "l"(a), "l"(b), "l"(c)); return r;
}
__device__ __forceinline__ uint64_t f2neg(uint64_t a) { return a ^ 0x8000000080000000ull; }
__device__ __forceinline__ uint64_t f2sub(uint64_t a, uint64_t b) { return f2add(a, f2neg(b)); }

__device__ __forceinline__ uint64_t pack2(float lo, float hi) {
    return ((uint64_t)__float_as_uint(hi) << 32) | (uint64_t)__float_as_uint(lo);
}
__device__ __forceinline__ float plo(uint64_t v) { return __uint_as_float((unsigned)v); }
__device__ __forceinline__ float phi(uint64_t v) { return __uint_as_float((unsigned)(v >> 32)); }

// ---------------------------------------------------------------------------
// Packed double-float (two independent df lanes)
// ---------------------------------------------------------------------------
struct DF2 { uint64_t h, l; };

__device__ __forceinline__ DF2 df2_make(uint64_t h, uint64_t l) { DF2 r; r.h = h; r.l = l; return r; }

__device__ __forceinline__ DF2 df2_twoprod(uint64_t a, uint64_t b) {
    uint64_t p = f2mul(a, b);
    uint64_t e = f2fma(a, b, f2neg(p));
    return df2_make(p, e);
}

__device__ __forceinline__ DF2 df2_add(DF2 a, DF2 b) {   // Knuth TwoSum + renorm
    uint64_t s  = f2add(a.h, b.h);
    uint64_t bp = f2sub(s, a.h);
    uint64_t ap = f2sub(s, bp);
    uint64_t eb = f2sub(b.h, bp);
    uint64_t ea = f2sub(a.h, ap);
    uint64_t e  = f2add(f2add(ea, eb), f2add(a.l, b.l));
    uint64_t h  = f2add(s, e);
    uint64_t l  = f2sub(e, f2sub(h, s));
    return df2_make(h, l);
}

__device__ __forceinline__ DF2 df2_neg(DF2 a) { return df2_make(f2neg(a.h), f2neg(a.l)); }
__device__ __forceinline__ DF2 df2_sub(DF2 a, DF2 b) { return df2_add(a, df2_neg(b)); }
__device__ __forceinline__ DF2 df2_scale2(DF2 a) { return df2_make(f2add(a.h, a.h), f2add(a.l, a.l)); }

// (packed float w, same in both lanes) * df
__device__ __forceinline__ DF2 df2_mulf(uint64_t w, DF2 a) {
    uint64_t p = f2mul(w, a.h);
    uint64_t e = f2fma(w, a.h, f2neg(p));
    e = f2fma(w, a.l, e);
    uint64_t h = f2add(p, e);
    uint64_t l = f2sub(e, f2sub(h, p));
    return df2_make(h, l);
}

__device__ __forceinline__ DF2 df2_sqr(DF2 a) {
    uint64_t p = f2mul(a.h, a.h);
    uint64_t e = f2fma(a.h, a.h, f2neg(p));
    e = f2fma(f2add(a.h, a.h), a.l, e);
    uint64_t h = f2add(p, e);
    uint64_t l = f2sub(e, f2sub(h, p));
    return df2_make(h, l);
}

// ---------------------------------------------------------------------------
// Scalar df helpers (decision logic only)
// ---------------------------------------------------------------------------
struct DF { float h, l; };
__device__ __forceinline__ DF df_make(float h, float l) { DF r; r.h = h; r.l = l; return r; }
__device__ __forceinline__ DF df_mul_df(DF a, DF b) {
    float p = a.h * b.h;
    float e = fmaf(a.h, b.h, -p);
    e = e + (a.h * b.l + a.l * b.h);
    float h = p + e;
    float l = e - (h - p);
    return df_make(h, l);
}
__device__ __forceinline__ bool df_lt(DF a, DF b) {
    return (a.h < b.h) || (a.h == b.h && a.l < b.l);
}
__device__ __forceinline__ DF df_abs(DF a) {
    bool neg = (a.h < 0.0f) || (a.h == 0.0f && a.l < 0.0f);
    return neg ? df_make(-a.h, -a.l) : a;
}
__device__ __forceinline__ bool df_pos(DF a) {
    return (a.h > 0.0f) || (a.h == 0.0f && a.l > 0.0f);
}

__device__ __forceinline__ unsigned char dir_bin(DF gx, DF gy) {
    const double T1d = 0.41421356237309503;  // tan(22.5 deg)
    const double T2d = 2.414213562373095;    // tan(67.5 deg)
    const DF T1 = df_make((float)T1d, (float)(T1d - (double)(float)T1d));
    const DF T2 = df_make((float)T2d, (float)(T2d - (double)(float)T2d));
    DF ax = df_abs(gx), ay = df_abs(gy);
    if (df_lt(ay, df_mul_df(T1, ax)))       return 0;
    if (!df_lt(ay, df_mul_df(T2, ax)))      return 2;
    return (df_pos(gx) == df_pos(gy)) ? 1 : 3;
}

// exact-ish compare of df pairs (g2 values)
__device__ __forceinline__ bool dfp_gt(float ah, float al, float bh, float bl) {
    return (ah > bh) || (ah == bh && al > bl);
}

// ---------------------------------------------------------------------------
// Fused front: img -> gauss(sep df2) -> sobel(df2) -> NMS -> sup (+min/max)
// ---------------------------------------------------------------------------
__global__ __launch_bounds__(NTHR) void fused_front_kernel(const float* __restrict__ img) {
    __shared__ uint64_t s_img[24][40];              // packed (b, b+1) image
    __shared__ uint64_t s_row_h[24][36], s_row_l[24][36];
    __shared__ uint64_t s_sm_h[20][36],  s_sm_l[20][36];
    __shared__ uint64_t s_g2_h[18][34],  s_g2_l[18][34];
    __shared__ uchar2   s_bin[18][34];
    __shared__ float    smin[NTHR / 32], smax[NTHR / 32];

    const int x0 = blockIdx.x * TX;
    const int y0 = blockIdx.y * TY;
    const int p  = blockIdx.z;                       // batch pair
    const float* p0 = img + (size_t)(2 * p)     * IMG_HW;
    const float* p1 = img + (size_t)(2 * p + 1) * IMG_HW;
    const int tid = threadIdx.x;

    // reference 1D fp32 gaussian weights (same constants as the passing R6 kernel)
    const float w5[5] = {0.054488684549640294f, 0.24420134200323337f,
                         0.4026199468935272f,  0.24420134200323337f,
                         0.054488684549640294f};

    // ---- Stage 1: load image tile (reflect once) ----
    for (int i = tid; i < 24 * 40; i += NTHR) {
        const int yy = i / 40, xx = i - yy * 40;
        const int gx = refl(x0 - 4 + xx, IMG_W);
        const int gy = refl(y0 - 4 + yy, IMG_H);
        s_img[yy][xx] = pack2(p0[gy * IMG_W + gx], p1[gy * IMG_W + gx]);
    }
    __syncthreads();

    // ---- Stage 2: row convolution (x), df2 exact ----
    for (int i = tid; i < 24 * 36; i += NTHR) {
        const int ry = i / 36, rx = i - ry * 36;
        DF2 acc = df2_twoprod(pack2(w5[0], w5[0]), s_img[ry][rx]);
#pragma unroll
        for (int k = 1; k < 5; k++)
            acc = df2_add(acc, df2_twoprod(pack2(w5[k], w5[k]), s_img[ry][rx + k]));
        s_row_h[ry][rx] = acc.h;
        s_row_l[ry][rx] = acc.l;
    }
    __syncthreads();

    // ---- Stage 3: column convolution (y), df2 ----
    for (int i = tid; i < 20 * 36; i += NTHR) {
        const int sy = i / 36, sx = i - sy * 36;
        DF2 acc = df2_mulf(pack2(w5[0], w5[0]),
                           df2_make(s_row_h[sy][sx], s_row_l[sy][sx]));
#pragma unroll
        for (int k = 1; k < 5; k++)
            acc = df2_add(acc, df2_mulf(pack2(w5[k], w5[k]),
                                        df2_make(s_row_h[sy + k][sx], s_row_l[sy + k][sx])));
        s_sm_h[sy][sx] = acc.h;
        s_sm_l[sy][sx] = acc.l;
    }
    __syncthreads();

    // ---- Stage 4: Sobel -> grad^2 (df2) + direction bins (scalar df) ----
    for (int i = tid; i < 18 * 34; i += NTHR) {
        const int jy = i / 34, jx = i - jy * 34;
        DF2 v00 = df2_make(s_sm_h[jy + 0][jx + 0], s_sm_l[jy + 0][jx + 0]);
        DF2 v01 = df2_make(s_sm_h[jy + 0][jx + 1], s_sm_l[jy + 0][jx + 1]);
        DF2 v02 = df2_make(s_sm_h[jy + 0][jx + 2], s_sm_l[jy + 0][jx + 2]);
        DF2 v10 = df2_make(s_sm_h[jy + 1][jx + 0], s_sm_l[jy + 1][jx + 0]);
        DF2 v12 = df2_make(s_sm_h[jy + 1][jx + 2], s_sm_l[jy + 1][jx + 2]);
        DF2 v20 = df2_make(s_sm_h[jy + 2][jx + 0], s_sm_l[jy + 2][jx + 0]);
        DF2 v21 = df2_make(s_sm_h[jy + 2][jx + 1], s_sm_l[jy + 2][jx + 1]);
        DF2 v22 = df2_make(s_sm_h[jy + 2][jx + 2], s_sm_l[jy + 2][jx + 2]);

        DF2 gx = df2_add(df2_add(df2_sub(v02, v00),
                                 df2_scale2(df2_sub(v12, v10))),
                         df2_sub(v22, v20));
        DF2 gy = df2_sub(df2_add(df2_add(v00, df2_scale2(v01)), v02),
                         df2_add(df2_add(v20, df2_scale2(v21)), v22));
        DF2 g2 = df2_add(df2_sqr(gx), df2_sqr(gy));

        s_g2_h[jy][jx] = g2.h;
        s_g2_l[jy][jx] = g2.l;

        uchar2 bb;
        bb.x = dir_bin(df_make(plo(gx.h), plo(gx.l)), df_make(plo(gy.h), plo(gy.l)));
        bb.y = dir_bin(df_make(phi(gx.h), phi(gx.l)), df_make(phi(gy.h), phi(gy.l)));
        s_bin[jy][jx] = bb;
    }
    __syncthreads();

    // ---- Stage 5: NMS + sup + fused block min/max ----
    const int tx = tid & (TX - 1);
    const int ty = tid >> 5;

    const uint64_t c_h = s_g2_h[ty + 1][tx + 1];
    const uint64_t c_l = s_g2_l[ty + 1][tx + 1];
    const uchar2  bin2 = s_bin[ty + 1][tx + 1];

    float sup[2];
#pragma unroll
    for (int comp = 0; comp < 2; comp++) {
        const int bin = comp ? bin2.y : bin2.x;
        int ay, ax_, by, bx_;
        if (bin == 0)      { ay = ty + 1; ax_ = tx + 2; by = ty + 1; bx_ = tx + 0; } // E,W
        else if (bin == 2) { ay = ty + 0; ax_ = tx + 1; by = ty + 2; bx_ = tx + 1; } // N,S
        else if (bin == 1) { ay = ty + 2; ax_ = tx + 0; by = ty + 0; bx_ = tx + 2; } // SW,NE
        else               { ay = ty + 2; ax_ = tx + 2; by = ty + 0; bx_ = tx + 0; } // SE,NW

        float ch, cl, nah, nal, nbh, nbl;
        if (comp == 0) {
            ch = plo(c_h); cl = plo(c_l);
            nah = plo(s_g2_h[ay][ax_]); nal = plo(s_g2_l[ay][ax_]);
            nbh = plo(s_g2_h[by][bx_]); nbl = plo(s_g2_l[by][bx_]);
        } else {
            ch = phi(c_h); cl = phi(c_l);
            nah = phi(s_g2_h[ay][ax_]); nal = phi(s_g2_l[ay][ax_]);
            nbh = phi(s_g2_h[by][bx_]); nbl = phi(s_g2_l[by][bx_]);
        }

        float sv = 0.0f;
        if (dfp_gt(ch, cl, nah, nal) && dfp_gt(ch, cl, nbh, nbl)) {
            float r = sqrtf(ch);
            if (ch > 1.1754944e-38f) {        // Newton toward sqrt(ch + cl)
                float resid = fmaf(-r, r, ch) + cl;
                r = fmaf(resid, 0.5f / r, r);
            }
            sv = r;
        }
        sup[comp] = sv;
    }

    g_sup2[(size_t)p * IMG_HW + (size_t)(y0 + ty) * IMG_W + (x0 + tx)] =
        make_float2(sup[0], sup[1]);

    // block min/max (sup >= 0 -> uint order == float order)
    float vmin = fminf(sup[0], sup[1]);
    float vmax = fmaxf(sup[0], sup[1]);
#pragma unroll
    for (int off = 16; off > 0; off >>= 1) {
        vmin = fminf(vmin, __shfl_xor_sync(0xFFFFFFFF, vmin, off));
        vmax = fmaxf(vmax, __shfl_xor_sync(0xFFFFFFFF, vmax, off));
    }
    const int wid = tid >> 5;
    if ((tid & 31) == 0) { smin[wid] = vmin; smax[wid] = vmax; }
    __syncthreads();
    if (tid == 0) {
        float bmin = smin[0], bmax = smax[0];
#pragma unroll
        for (int i = 1; i < NTHR / 32; i++) {
            bmin = fminf(bmin, smin[i]);
            bmax = fmaxf(bmax, smax[i]);
        }
        atomicMin(&g_min_bits, __float_as_uint(bmin));
        atomicMax(&g_max_bits, __float_as_uint(bmax));
    }
}

// ---------------------------------------------------------------------------
// init reduction scalars
// ---------------------------------------------------------------------------
__global__ void init_minmax_kernel() {
    g_min_bits = 0x7F800000u;  // +inf
    g_max_bits = 0u;           // 0.0f
}

// ---------------------------------------------------------------------------
// Fused back: sup -> strong(smem) -> hysteresis conv -> mask
// ---------------------------------------------------------------------------
__global__ __launch_bounds__(NTHR) void fused_back_kernel(float* __restrict__ out) {
    __shared__ float2   s_sup[18][34];
    __shared__ uint64_t s_str[18][34];   // packed strong pair

    const int x0 = blockIdx.x * TX;
    const int y0 = blockIdx.y * TY;
    const int p  = blockIdx.z;
    const int tid = threadIdx.x;
    const float2* sup_base = g_sup2 + (size_t)p * IMG_HW;

    const float mn = __uint_as_float(g_min_bits);
    const float mx = __uint_as_float(g_max_bits);
    const float high = mn + (mx - mn) * 0.25f;
    const float low  = mn + (mx - mn) * 0.1f;

    // load sup tile with halo + compute strong
    for (int i = tid; i < 18 * 34; i += NTHR) {
        const int yy = i / 34, xx = i - yy * 34;
        const int gx = refl(x0 - 1 + xx, IMG_W);
        const int gy = refl(y0 - 1 + yy, IMG_H);
        const float2 sv = sup_base[gy * IMG_W + gx];
        s_sup[yy][xx] = sv;
        s_str[yy][xx] = pack2(sigm(100.0f * (sv.x - high)),
                              sigm(100.0f * (sv.y - high)));
    }
    __syncthreads();

    const int tx = tid & (TX - 1);
    const int ty = tid >> 5;

    // 3x3 sum of strong (packed adds)
    uint64_t hs = s_str[ty + 0][tx + 0];
    hs = f2add(hs, s_str[ty + 0][tx + 1]);
    hs = f2add(hs, s_str[ty + 0][tx + 2]);
    hs = f2add(hs, s_str[ty + 1][tx + 0]);
    hs = f2add(hs, s_str[ty + 1][tx + 1]);
    hs = f2add(hs, s_str[ty + 1][tx + 2]);
    hs = f2add(hs, s_str[ty + 2][tx + 0]);
    hs = f2add(hs, s_str[ty + 2][tx + 1]);
    hs = f2add(hs, s_str[ty + 2][tx + 2]);

    const uint64_t sc = s_str[ty + 1][tx + 1];
    const float2  sv  = s_sup[ty + 1][tx + 1];

    const float s0 = plo(sc), s1 = phi(sc);
    const float w0 = sigm(100.0f * (sv.x - low)) * (1.0f - s0);
    const float w1 = sigm(100.0f * (sv.y - low)) * (1.0f - s1);
    const float m0 = s0 + w0 * sigm(100.0f * (plo(hs) - 0.5f));
    const float m1 = s1 + w1 * sigm(100.0f * (phi(hs) - 0.5f));

    const size_t idx = (size_t)(y0 + ty) * IMG_W + (x0 + tx);
    out[(size_t)(2 * p)     * IMG_HW + idx] = m0;
    out[(size_t)(2 * p + 1) * IMG_HW + idx] = m1;
}

// ---------------------------------------------------------------------------
extern "C" void kernel_launch(void* const* d_in, const int* in_sizes, int n_in,
                              void* d_out, int out_size) {
    const float* image = (const float*)d_in[0];
    float* out = (float*)d_out;

    init_minmax_kernel<<<1, 1>>>();

    dim3 grd(IMG_W / TX, IMG_H / TY, NPAIR);
    fused_front_kernel<<<grd, NTHR>>>(image);
    fused_back_kernel<<<grd, NTHR>>>(out);
}

// round 9
// speedup vs baseline: 6.0832x; 1.2275x over previous
#include <cuda_runtime.h>
#include <math.h>
#include <stdint.h>

#define IMG_W 1024
#define IMG_H 1024
#define IMG_B 8
#define IMG_HW (IMG_H * IMG_W)

#define TX 32
#define TY 16
#define NTHR 512
#define NPAIR 4
#define NBLOCKS ((IMG_W / TX) * (IMG_H / TY) * NPAIR)

// Tile regions (offsets rel. to output tile origin):
//   img : 40 x 24 (-4,-4)   row-conv : 36 x 24 (-2,-4)
//   sm  : 36 x 20 (-2,-2)   g2/bin   : 34 x 18 (-1,-1)

// ---------------------------------------------------------------------------
// Scratch (allocation-free rule: __device__ globals; zero-initialized at load)
// ---------------------------------------------------------------------------
__device__ float2 g_sup2[(size_t)NPAIR * IMG_HW];  // pair-interleaved sup
__device__ unsigned int g_max_bits;   // 0-init; reset to 0 by last back block
__device__ unsigned int g_done;       // 0-init; reset to 0 by last back block

__device__ __forceinline__ int refl(int i, int n) {
    if (i < 0) i = -i;
    if (i >= n) i = 2 * n - 2 - i;
    return i;
}
__device__ __forceinline__ float sigm(float x) { return 1.0f / (1.0f + expf(-x)); }

// ---------------------------------------------------------------------------
// Packed f32x2 primitives (FFMA2 path)
// ---------------------------------------------------------------------------
__device__ __forceinline__ uint64_t f2add(uint64_t a, uint64_t b) {
    uint64_t r; asm("add.rn.f32x2 %0, %1, %2;" : "=l"(r) : "l"(a), "l"(b)); return r;
}
__device__ __forceinline__ uint64_t f2mul(uint64_t a, uint64_t b) {
    uint64_t r; asm("mul.rn.f32x2 %0, %1, %2;" : "=l"(r) : "l"(a), "l"(b)); return r;
}
__device__ __forceinline__ uint64_t f2fma(uint64_t a, uint64_t b, uint64_t c) {
    uint64_t r; asm("fma.rn.f32x2 %0, %1, %2, %3;" : "=l"(r) : "l"(a), "l"(b), "l"(c)); return r;
}
__device__ __forceinline__ uint64_t f2neg(uint64_t a) { return a ^ 0x8000000080000000ull; }

__device__ __forceinline__ uint64_t pack2(float lo, float hi) {
    return ((uint64_t)__float_as_uint(hi) << 32) | (uint64_t)__float_as_uint(lo);
}
__device__ __forceinline__ float plo(uint64_t v) { return __uint_as_float((unsigned)v); }
__device__ __forceinline__ float phi(uint64_t v) { return __uint_as_float((unsigned)(v >> 32)); }

#define NEG1_PK 0xBF800000BF800000ull   // packed (-1.0f, -1.0f)

// sub via fma: a - b
__device__ __forceinline__ uint64_t f2sub(uint64_t a, uint64_t b) {
    return f2fma(b, NEG1_PK, a);
}

// exact product: (p, e)
__device__ __forceinline__ void f2_twoprod(uint64_t a, uint64_t b,
                                           uint64_t& p, uint64_t& e) {
    p = f2mul(a, b);
    e = f2fma(a, b, f2neg(p));
}

// compensated accumulate: (ah, al) += (p, e).  TwoSum on highs, errors -> al.
__device__ __forceinline__ void f2_acc(uint64_t& ah, uint64_t& al,
                                       uint64_t p, uint64_t e) {
    uint64_t s  = f2add(ah, p);
    uint64_t bp = f2fma(ah, NEG1_PK, s);   // s - ah
    uint64_t ap = f2fma(bp, NEG1_PK, s);   // s - bp
    uint64_t eb = f2fma(bp, NEG1_PK, p);   // p - bp
    uint64_t ea = f2fma(ap, NEG1_PK, ah);  // ah - ap
    ah = s;
    al = f2add(al, f2add(f2add(ea, eb), e));
}

// Fast2Sum renorm (requires nothing; produces |l| <= 0.5 ulp(h))
__device__ __forceinline__ void f2_renorm(uint64_t& h, uint64_t& l) {
    uint64_t hh = f2add(h, l);
    uint64_t t  = f2fma(h, NEG1_PK, hh);   // hh - h
    l = f2fma(t, NEG1_PK, l);              // l - t
    h = hh;
}

// ---------------------------------------------------------------------------
// Scalar df helpers (decision logic only; operands renormalized)
// ---------------------------------------------------------------------------
struct DF { float h, l; };
__device__ __forceinline__ DF df_make(float h, float l) { DF r; r.h = h; r.l = l; return r; }
__device__ __forceinline__ DF df_mul_df(DF a, DF b) {
    float p = a.h * b.h;
    float e = fmaf(a.h, b.h, -p);
    e = e + (a.h * b.l + a.l * b.h);
    float h = p + e;
    float l = e - (h - p);
    return df_make(h, l);
}
__device__ __forceinline__ bool df_lt(DF a, DF b) {
    return (a.h < b.h) || (a.h == b.h && a.l < b.l);
}
__device__ __forceinline__ DF df_abs(DF a) {
    bool neg = (a.h < 0.0f) || (a.h == 0.0f && a.l < 0.0f);
    return neg ? df_make(-a.h, -a.l) : a;
}
__device__ __forceinline__ bool df_pos(DF a) {
    return (a.h > 0.0f) || (a.h == 0.0f && a.l > 0.0f);
}

__device__ __forceinline__ unsigned char dir_bin(DF gx, DF gy) {
    const double T1d = 0.41421356237309503;  // tan(22.5 deg)
    const double T2d = 2.414213562373095;    // tan(67.5 deg)
    const DF T1 = df_make((float)T1d, (float)(T1d - (double)(float)T1d));
    const DF T2 = df_make((float)T2d, (float)(T2d - (double)(float)T2d));
    DF ax = df_abs(gx), ay = df_abs(gy);
    if (df_lt(ay, df_mul_df(T1, ax)))  return 0;   // E/W
    if (!df_lt(ay, df_mul_df(T2, ax))) return 2;   // N/S
    return (df_pos(gx) == df_pos(gy)) ? 1 : 3;     // SW/NE : SE/NW
}

// lexicographic compare of renormalized df pairs
__device__ __forceinline__ bool dfp_gt(float ah, float al, float bh, float bl) {
    return (ah > bh) || (ah == bh && al > bl);
}

// ---------------------------------------------------------------------------
// Fused front: img -> sep gauss (df2) -> sobel (df2) -> NMS -> sup (+max)
// ---------------------------------------------------------------------------
__global__ __launch_bounds__(NTHR) void fused_front_kernel(const float* __restrict__ img) {
    __shared__ uint64_t s_img[24][40];
    __shared__ uint64_t s_row_h[24][36], s_row_l[24][36];
    __shared__ uint64_t s_sm_h[20][36],  s_sm_l[20][36];
    __shared__ uint64_t s_g2_h[18][34],  s_g2_l[18][34];
    __shared__ uchar2   s_bin[18][34];
    __shared__ float    smax[NTHR / 32];

    const int x0 = blockIdx.x * TX;
    const int y0 = blockIdx.y * TY;
    const int p  = blockIdx.z;
    const float* p0 = img + (size_t)(2 * p)     * IMG_HW;
    const float* p1 = img + (size_t)(2 * p + 1) * IMG_HW;
    const int tid = threadIdx.x;

    const float w5[5] = {0.054488684549640294f, 0.24420134200323337f,
                         0.4026199468935272f,  0.24420134200323337f,
                         0.054488684549640294f};
    uint64_t W[5];
#pragma unroll
    for (int k = 0; k < 5; k++) W[k] = pack2(w5[k], w5[k]);

    // ---- Stage 1: load image tile (reflect once) ----
    for (int i = tid; i < 24 * 40; i += NTHR) {
        const int yy = i / 40, xx = i - yy * 40;
        const int gx = refl(x0 - 4 + xx, IMG_W);
        const int gy = refl(y0 - 4 + yy, IMG_H);
        const int gi = gy * IMG_W + gx;
        s_img[yy][xx] = pack2(p0[gi], p1[gi]);
    }
    __syncthreads();

    // ---- Stage 2: row convolution (x), compensated ----
    for (int i = tid; i < 24 * 36; i += NTHR) {
        const int ry = i / 36, rx = i - ry * 36;
        uint64_t ah, al;
        f2_twoprod(W[0], s_img[ry][rx], ah, al);
#pragma unroll
        for (int k = 1; k < 5; k++) {
            uint64_t pp, ee;
            f2_twoprod(W[k], s_img[ry][rx + k], pp, ee);
            f2_acc(ah, al, pp, ee);
        }
        s_row_h[ry][rx] = ah;
        s_row_l[ry][rx] = al;
    }
    __syncthreads();

    // ---- Stage 3: column convolution (y), compensated ----
    for (int i = tid; i < 20 * 36; i += NTHR) {
        const int sy = i / 36, sx = i - sy * 36;
        uint64_t h0 = s_row_h[sy][sx], l0 = s_row_l[sy][sx];
        uint64_t ah = f2mul(W[0], h0);
        uint64_t al = f2fma(W[0], h0, f2neg(ah));
        al = f2fma(W[0], l0, al);
#pragma unroll
        for (int k = 1; k < 5; k++) {
            uint64_t hk = s_row_h[sy + k][sx], lk = s_row_l[sy + k][sx];
            uint64_t pp = f2mul(W[k], hk);
            uint64_t ee = f2fma(W[k], hk, f2neg(pp));
            ee = f2fma(W[k], lk, ee);
            f2_acc(ah, al, pp, ee);
        }
        s_sm_h[sy][sx] = ah;
        s_sm_l[sy][sx] = al;
    }
    __syncthreads();

    // ---- Stage 4: Sobel -> grad^2 + bins (bins only where NMS reads them) ----
    for (int i = tid; i < 18 * 34; i += NTHR) {
        const int jy = i / 34, jx = i - jy * 34;
        const uint64_t v00h = s_sm_h[jy + 0][jx + 0], v00l = s_sm_l[jy + 0][jx + 0];
        const uint64_t v01h = s_sm_h[jy + 0][jx + 1], v01l = s_sm_l[jy + 0][jx + 1];
        const uint64_t v02h = s_sm_h[jy + 0][jx + 2], v02l = s_sm_l[jy + 0][jx + 2];
        const uint64_t v10h = s_sm_h[jy + 1][jx + 0], v10l = s_sm_l[jy + 1][jx + 0];
        const uint64_t v12h = s_sm_h[jy + 1][jx + 2], v12l = s_sm_l[jy + 1][jx + 2];
        const uint64_t v20h = s_sm_h[jy + 2][jx + 0], v20l = s_sm_l[jy + 2][jx + 0];
        const uint64_t v21h = s_sm_h[jy + 2][jx + 1], v21l = s_sm_l[jy + 2][jx + 1];
        const uint64_t v22h = s_sm_h[jy + 2][jx + 2], v22l = s_sm_l[jy + 2][jx + 2];

        // gx = v02 - v00 + 2*(v12 - v10) + v22 - v20
        uint64_t gxh = v02h, gxl = v02l;
        f2_acc(gxh, gxl, f2neg(v00h), f2neg(v00l));
        f2_acc(gxh, gxl, f2add(v12h, v12h), f2add(v12l, v12l));
        f2_acc(gxh, gxl, f2neg(f2add(v10h, v10h)), f2neg(f2add(v10l, v10l)));
        f2_acc(gxh, gxl, v22h, v22l);
        f2_acc(gxh, gxl, f2neg(v20h), f2neg(v20l));
        f2_renorm(gxh, gxl);

        // gy = v00 + 2*v01 + v02 - v20 - 2*v21 - v22
        uint64_t gyh = v00h, gyl = v00l;
        f2_acc(gyh, gyl, f2add(v01h, v01h), f2add(v01l, v01l));
        f2_acc(gyh, gyl, v02h, v02l);
        f2_acc(gyh, gyl, f2neg(v20h), f2neg(v20l));
        f2_acc(gyh, gyl, f2neg(f2add(v21h, v21h)), f2neg(f2add(v21l, v21l)));
        f2_acc(gyh, gyl, f2neg(v22h), f2neg(v22l));
        f2_renorm(gyh, gyl);

        // g2 = gx^2 + gy^2 (compensated), renormalized for exact compares
        uint64_t pa = f2mul(gxh, gxh);
        uint64_t ea = f2fma(gxh, gxh, f2neg(pa));
        ea = f2fma(f2add(gxh, gxh), gxl, ea);
        uint64_t pb = f2mul(gyh, gyh);
        uint64_t eb = f2fma(gyh, gyh, f2neg(pb));
        eb = f2fma(f2add(gyh, gyh), gyl, eb);
        uint64_t g2h = pa, g2l = ea;
        f2_acc(g2h, g2l, pb, eb);
        f2_renorm(g2h, g2l);

        s_g2_h[jy][jx] = g2h;
        s_g2_l[jy][jx] = g2l;

        // bins only needed at output-interior cells
        if (jy >= 1 && jy <= TY && jx >= 1 && jx <= TX) {
            uchar2 bb;
            bb.x = dir_bin(df_make(plo(gxh), plo(gxl)), df_make(plo(gyh), plo(gyl)));
            bb.y = dir_bin(df_make(phi(gxh), phi(gxl)), df_make(phi(gyh), phi(gyl)));
            s_bin[jy][jx] = bb;
        }
    }
    __syncthreads();

    // ---- Stage 5: NMS + sup + fused block max ----
    const int tx = tid & (TX - 1);
    const int ty = tid >> 5;

    const uint64_t c_h = s_g2_h[ty + 1][tx + 1];
    const uint64_t c_l = s_g2_l[ty + 1][tx + 1];
    const uchar2  bin2 = s_bin[ty + 1][tx + 1];

    float sup[2];
#pragma unroll
    for (int comp = 0; comp < 2; comp++) {
        const int bin = comp ? bin2.y : bin2.x;
        int ay, ax_, by, bx_;
        if (bin == 0)      { ay = ty + 1; ax_ = tx + 2; by = ty + 1; bx_ = tx + 0; } // E,W
        else if (bin == 2) { ay = ty + 0; ax_ = tx + 1; by = ty + 2; bx_ = tx + 1; } // N,S
        else if (bin == 1) { ay = ty + 2; ax_ = tx + 0; by = ty + 0; bx_ = tx + 2; } // SW,NE
        else               { ay = ty + 2; ax_ = tx + 2; by = ty + 0; bx_ = tx + 0; } // SE,NW

        float ch, cl, nah, nal, nbh, nbl;
        if (comp == 0) {
            ch = plo(c_h); cl = plo(c_l);
            nah = plo(s_g2_h[ay][ax_]); nal = plo(s_g2_l[ay][ax_]);
            nbh = plo(s_g2_h[by][bx_]); nbl = plo(s_g2_l[by][bx_]);
        } else {
            ch = phi(c_h); cl = phi(c_l);
            nah = phi(s_g2_h[ay][ax_]); nal = phi(s_g2_l[ay][ax_]);
            nbh = phi(s_g2_h[by][bx_]); nbl = phi(s_g2_l[by][bx_]);
        }

        float sv = 0.0f;
        if (dfp_gt(ch, cl, nah, nal) && dfp_gt(ch, cl, nbh, nbl)) {
            float r = sqrtf(ch);
            if (ch > 1.1754944e-38f) {            // Newton toward sqrt(ch + cl)
                float resid = fmaf(-r, r, ch) + cl;
                r = fmaf(resid, 0.5f / r, r);
            }
            sv = r;
        }
        sup[comp] = sv;
    }

    g_sup2[(size_t)p * IMG_HW + (size_t)(y0 + ty) * IMG_W + (x0 + tx)] =
        make_float2(sup[0], sup[1]);

    // block max (sup >= 0 -> uint order == float order); min is provably 0
    float vmax = fmaxf(sup[0], sup[1]);
#pragma unroll
    for (int off = 16; off > 0; off >>= 1)
        vmax = fmaxf(vmax, __shfl_xor_sync(0xFFFFFFFF, vmax, off));
    const int wid = tid >> 5;
    if ((tid & 31) == 0) smax[wid] = vmax;
    __syncthreads();
    if (tid == 0) {
        float bmax = smax[0];
#pragma unroll
        for (int i = 1; i < NTHR / 32; i++) bmax = fmaxf(bmax, smax[i]);
        atomicMax(&g_max_bits, __float_as_uint(bmax));
    }
}

// ---------------------------------------------------------------------------
// Fused back: sup -> strong (smem) -> hysteresis conv -> mask; resets g_max
// ---------------------------------------------------------------------------
__global__ __launch_bounds__(NTHR) void fused_back_kernel(float* __restrict__ out) {
    __shared__ float2   s_sup[18][34];
    __shared__ uint64_t s_str[18][34];

    const int x0 = blockIdx.x * TX;
    const int y0 = blockIdx.y * TY;
    const int p  = blockIdx.z;
    const int tid = threadIdx.x;
    const float2* sup_base = g_sup2 + (size_t)p * IMG_HW;

    // min(sup) == 0 exactly (NMS always suppresses some pixels), so:
    const float mx   = __uint_as_float(g_max_bits);
    const float high = mx * 0.25f;
    const float low  = mx * 0.1f;

    for (int i = tid; i < 18 * 34; i += NTHR) {
        const int yy = i / 34, xx = i - yy * 34;
        const int gx = refl(x0 - 1 + xx, IMG_W);
        const int gy = refl(y0 - 1 + yy, IMG_H);
        const float2 sv = sup_base[gy * IMG_W + gx];
        s_sup[yy][xx] = sv;
        s_str[yy][xx] = pack2(sigm(100.0f * (sv.x - high)),
                              sigm(100.0f * (sv.y - high)));
    }
    __syncthreads();   // also guarantees every thread consumed g_max_bits

    const int tx = tid & (TX - 1);
    const int ty = tid >> 5;

    uint64_t hs = s_str[ty + 0][tx + 0];
    hs = f2add(hs, s_str[ty + 0][tx + 1]);
    hs = f2add(hs, s_str[ty + 0][tx + 2]);
    hs = f2add(hs, s_str[ty + 1][tx + 0]);
    hs = f2add(hs, s_str[ty + 1][tx + 1]);
    hs = f2add(hs, s_str[ty + 1][tx + 2]);
    hs = f2add(hs, s_str[ty + 2][tx + 0]);
    hs = f2add(hs, s_str[ty + 2][tx + 1]);
    hs = f2add(hs, s_str[ty + 2][tx + 2]);

    const uint64_t sc = s_str[ty + 1][tx + 1];
    const float2  sv  = s_sup[ty + 1][tx + 1];

    const float s0 = plo(sc), s1 = phi(sc);
    const float w0 = sigm(100.0f * (sv.x - low)) * (1.0f - s0);
    const float w1 = sigm(100.0f * (sv.y - low)) * (1.0f - s1);
    const float m0 = s0 + w0 * sigm(100.0f * (plo(hs) - 0.5f));
    const float m1 = s1 + w1 * sigm(100.0f * (phi(hs) - 0.5f));

    const size_t idx = (size_t)(y0 + ty) * IMG_W + (x0 + tx);
    out[(size_t)(2 * p)     * IMG_HW + idx] = m0;
    out[(size_t)(2 * p + 1) * IMG_HW + idx] = m1;

    // last-finishing block resets scalars for the next (graph-replayed) launch.
    // Safe: a block increments g_done only after its __syncthreads above, i.e.
    // after every one of its threads has consumed g_max_bits.
    if (tid == 0) {
        const unsigned t = atomicAdd(&g_done, 1u);
        if (t == (unsigned)(NBLOCKS - 1)) {
            g_max_bits = 0u;
            g_done = 0u;
        }
    }
}

// ---------------------------------------------------------------------------
extern "C" void kernel_launch(void* const* d_in, const int* in_sizes, int n_in,
                              void* d_out, int out_size) {
    const float* image = (const float*)d_in[0];
    float* out = (float*)d_out;

    dim3 grd(IMG_W / TX, IMG_H / TY, NPAIR);
    fused_front_kernel<<<grd, NTHR>>>(image);
    fused_back_kernel<<<grd, NTHR>>>(out);
}

// round 10
// speedup vs baseline: 6.1860x; 1.0169x over previous
#include <cuda_runtime.h>
#include <math.h>
#include <stdint.h>

#define IMG_W 1024
#define IMG_H 1024
#define IMG_B 8
#define IMG_HW (IMG_H * IMG_W)

#define TX 32
#define TY 16
#define NTHR 512
#define NPAIR 4
#define NBLOCKS ((IMG_W / TX) * (IMG_H / TY) * NPAIR)

// ---------------------------------------------------------------------------
// Scratch (allocation-free rule: __device__ globals; zero-initialized)
// ---------------------------------------------------------------------------
__device__ float2 g_sup2[(size_t)NPAIR * IMG_HW];
__device__ unsigned int g_max_bits;   // reset by last back block each launch
__device__ unsigned int g_done;

__device__ __forceinline__ int refl(int i, int n) {
    if (i < 0) i = -i;
    if (i >= n) i = 2 * n - 2 - i;
    return i;
}

// fast sigmoid: MUFU ex2 + approx reciprocal (error ~2^-22, smooth path only)
__device__ __forceinline__ float sigm(float x) {
    float e = __expf(-x);
    float d = 1.0f + e;
    float r; asm("rcp.approx.f32 %0, %1;" : "=f"(r) : "f"(d));
    return r;
}

// ---------------------------------------------------------------------------
// Packed f32x2 primitives
// ---------------------------------------------------------------------------
__device__ __forceinline__ uint64_t f2add(uint64_t a, uint64_t b) {
    uint64_t r; asm("add.rn.f32x2 %0, %1, %2;" : "=l"(r) : "l"(a), "l"(b)); return r;
}
__device__ __forceinline__ uint64_t f2mul(uint64_t a, uint64_t b) {
    uint64_t r; asm("mul.rn.f32x2 %0, %1, %2;" : "=l"(r) : "l"(a), "l"(b)); return r;
}
__device__ __forceinline__ uint64_t f2fma(uint64_t a, uint64_t b, uint64_t c) {
    uint64_t r; asm("fma.rn.f32x2 %0, %1, %2, %3;" : "=l"(r) : "l"(a), "l"(b), "l"(c)); return r;
}
__device__ __forceinline__ uint64_t f2neg(uint64_t a) { return a ^ 0x8000000080000000ull; }

__device__ __forceinline__ uint64_t pack2(float lo, float hi) {
    return ((uint64_t)__float_as_uint(hi) << 32) | (uint64_t)__float_as_uint(lo);
}
__device__ __forceinline__ float plo(uint64_t v) { return __uint_as_float((unsigned)v); }
__device__ __forceinline__ float phi(uint64_t v) { return __uint_as_float((unsigned)(v >> 32)); }

#define NEG1_PK 0xBF800000BF800000ull

__device__ __forceinline__ uint64_t f2sub(uint64_t a, uint64_t b) {
    return f2fma(b, NEG1_PK, a);
}

// compensated accumulate: (ah, al) += (p, e)
__device__ __forceinline__ void f2_acc(uint64_t& ah, uint64_t& al,
                                       uint64_t p, uint64_t e) {
    uint64_t s  = f2add(ah, p);
    uint64_t bp = f2fma(ah, NEG1_PK, s);
    uint64_t ap = f2fma(bp, NEG1_PK, s);
    uint64_t eb = f2fma(bp, NEG1_PK, p);
    uint64_t ea = f2fma(ap, NEG1_PK, ah);
    ah = s;
    al = f2add(al, f2add(f2add(ea, eb), e));
}

// Fast2Sum renorm
__device__ __forceinline__ void f2_renorm(uint64_t& h, uint64_t& l) {
    uint64_t hh = f2add(h, l);
    uint64_t t  = f2fma(h, NEG1_PK, hh);
    l = f2fma(t, NEG1_PK, l);
    h = hh;
}

// packed df-const × df: (Th,Tl) * (ah,al) -> (mh,ml), renormalized
__device__ __forceinline__ void df2_mul_const(uint64_t Th, uint64_t Tl,
                                              uint64_t ah, uint64_t al,
                                              uint64_t& mh, uint64_t& ml) {
    uint64_t p = f2mul(Th, ah);
    uint64_t e = f2fma(Th, ah, f2neg(p));
    e = f2fma(Th, al, e);
    e = f2fma(Tl, ah, e);
    mh = f2add(p, e);
    ml = f2sub(e, f2sub(mh, p));
}

// uint4 <-> (h,l) df pair
__device__ __forceinline__ uint4 pk4(uint64_t h, uint64_t l) {
    uint4 r; r.x = (unsigned)h; r.y = (unsigned)(h >> 32);
    r.z = (unsigned)l; r.w = (unsigned)(l >> 32); return r;
}
__device__ __forceinline__ void upk4(uint4 v, uint64_t& h, uint64_t& l) {
    h = ((uint64_t)v.y << 32) | v.x;
    l = ((uint64_t)v.w << 32) | v.z;
}

// lexicographic compare of renormalized df pairs
__device__ __forceinline__ bool dfp_gt(float ah, float al, float bh, float bl) {
    return (ah > bh) || (ah == bh && al > bl);
}

// ---------------------------------------------------------------------------
// Shared-memory overlay offsets (bytes), one 45128-byte buffer:
//   img (24x40 u64, 7680)   @ 0       live: S1-S2
//   row (24x36 uint4,13824) @ 7680    live: S2-S3
//   sm  (20x36 uint4,11520) @ 21504   live: S3-SC
//   d   (20x34 uint4,10880) @ 0       live: SC-SD   (over dead img/row-head)
//   s   (20x34 uint4,10880) @ 33024   live: SC-SD
//   g2  (18x34 uint4, 9792) @ 21504   live: SD-SE   (over dead sm)
//   bin (18x34 uchar2,1224) @ 43904   live: SD-SE
// ---------------------------------------------------------------------------
#define OFF_IMG 0
#define OFF_ROW 7680
#define OFF_SM  21504
#define OFF_D   0
#define OFF_S   33024
#define OFF_G2  21504
#define OFF_BIN 43904
#define SBUF_SZ 45128

// ---------------------------------------------------------------------------
// Fused front: img -> sep gauss -> sobel(d/s factored) -> NMS -> sup (+max)
// ---------------------------------------------------------------------------
__global__ __launch_bounds__(NTHR) void fused_front_kernel(const float* __restrict__ img) {
    __shared__ __align__(16) unsigned char sbuf[SBUF_SZ];
    __shared__ float smax[NTHR / 32];

    uint64_t (*s_img)[40] = (uint64_t(*)[40])(sbuf + OFF_IMG);
    uint4    (*s_row)[36] = (uint4(*)[36])(sbuf + OFF_ROW);
    uint4    (*s_sm )[36] = (uint4(*)[36])(sbuf + OFF_SM);
    uint4    (*s_d  )[34] = (uint4(*)[34])(sbuf + OFF_D);
    uint4    (*s_s  )[34] = (uint4(*)[34])(sbuf + OFF_S);
    uint4    (*s_g2 )[34] = (uint4(*)[34])(sbuf + OFF_G2);
    uchar2   (*s_bin)[34] = (uchar2(*)[34])(sbuf + OFF_BIN);

    const int x0 = blockIdx.x * TX;
    const int y0 = blockIdx.y * TY;
    const int p  = blockIdx.z;
    const float* p0 = img + (size_t)(2 * p)     * IMG_HW;
    const float* p1 = img + (size_t)(2 * p + 1) * IMG_HW;
    const int tid = threadIdx.x;

    const float w5[5] = {0.054488684549640294f, 0.24420134200323337f,
                         0.4026199468935272f,  0.24420134200323337f,
                         0.054488684549640294f};
    uint64_t W[5];
#pragma unroll
    for (int k = 0; k < 5; k++) W[k] = pack2(w5[k], w5[k]);

    // ---- S1: load image tile (reflect once) ----
    for (int i = tid; i < 24 * 40; i += NTHR) {
        const int yy = i / 40, xx = i - yy * 40;
        const int gx = refl(x0 - 4 + xx, IMG_W);
        const int gy = refl(y0 - 4 + yy, IMG_H);
        const int gi = gy * IMG_W + gx;
        s_img[yy][xx] = pack2(p0[gi], p1[gi]);
    }
    __syncthreads();

    // ---- S2: row gaussian (x), compensated ----
    for (int i = tid; i < 24 * 36; i += NTHR) {
        const int ry = i / 36, rx = i - ry * 36;
        uint64_t a0 = s_img[ry][rx];
        uint64_t ah = f2mul(W[0], a0);
        uint64_t al = f2fma(W[0], a0, f2neg(ah));
#pragma unroll
        for (int k = 1; k < 5; k++) {
            uint64_t ak = s_img[ry][rx + k];
            uint64_t pp = f2mul(W[k], ak);
            uint64_t ee = f2fma(W[k], ak, f2neg(pp));
            f2_acc(ah, al, pp, ee);
        }
        s_row[ry][rx] = pk4(ah, al);
    }
    __syncthreads();

    // ---- S3: column gaussian (y), compensated ----
    for (int i = tid; i < 20 * 36; i += NTHR) {
        const int sy = i / 36, sx = i - sy * 36;
        uint64_t h0, l0;
        upk4(s_row[sy][sx], h0, l0);
        uint64_t ah = f2mul(W[0], h0);
        uint64_t al = f2fma(W[0], h0, f2neg(ah));
        al = f2fma(W[0], l0, al);
#pragma unroll
        for (int k = 1; k < 5; k++) {
            uint64_t hk, lk;
            upk4(s_row[sy + k][sx], hk, lk);
            uint64_t pp = f2mul(W[k], hk);
            uint64_t ee = f2fma(W[k], hk, f2neg(pp));
            ee = f2fma(W[k], lk, ee);
            f2_acc(ah, al, pp, ee);
        }
        s_sm[sy][sx] = pk4(ah, al);
    }
    __syncthreads();

    // ---- SC: per-row sobel intermediates  d = v+ - v-,  s = v- + 2v0 + v+ ----
    for (int i = tid; i < 20 * 34; i += NTHR) {
        const int ry = i / 34, jx = i - ry * 34;
        uint64_t v0h, v0l, v1h, v1l, v2h, v2l;
        upk4(s_sm[ry][jx + 0], v0h, v0l);
        upk4(s_sm[ry][jx + 1], v1h, v1l);
        upk4(s_sm[ry][jx + 2], v2h, v2l);

        uint64_t dh = v2h, dl = v2l;
        f2_acc(dh, dl, f2neg(v0h), f2neg(v0l));

        uint64_t sh = v0h, sl = v0l;
        f2_acc(sh, sl, f2add(v1h, v1h), f2add(v1l, v1l));
        f2_acc(sh, sl, v2h, v2l);

        s_d[ry][jx] = pk4(dh, dl);
        s_s[ry][jx] = pk4(sh, sl);
    }
    __syncthreads();

    // ---- SD: gx = d0+2d1+d2, gy = s0-s2, g2 = gx^2+gy^2, bins (interior) ----
    const uint64_t T1H = pack2(0.41421357f,  0.41421357f);   // hi(tan22.5)
    const uint64_t T1L = pack2(-7.3716195e-9f, -7.3716195e-9f);
    const uint64_t T2H = pack2(2.4142137f,   2.4142137f);    // hi(tan67.5)
    const uint64_t T2L = pack2(-1.3773958e-7f, -1.3773958e-7f);

    for (int i = tid; i < 18 * 34; i += NTHR) {
        const int jy = i / 34, jx = i - jy * 34;
        uint64_t d0h, d0l, d1h, d1l, d2h, d2l, s0h, s0l, s2h, s2l;
        upk4(s_d[jy + 0][jx], d0h, d0l);
        upk4(s_d[jy + 1][jx], d1h, d1l);
        upk4(s_d[jy + 2][jx], d2h, d2l);
        upk4(s_s[jy + 0][jx], s0h, s0l);
        upk4(s_s[jy + 2][jx], s2h, s2l);

        uint64_t gxh = d0h, gxl = d0l;
        f2_acc(gxh, gxl, f2add(d1h, d1h), f2add(d1l, d1l));
        f2_acc(gxh, gxl, d2h, d2l);
        f2_renorm(gxh, gxl);

        uint64_t gyh = s0h, gyl = s0l;
        f2_acc(gyh, gyl, f2neg(s2h), f2neg(s2l));
        f2_renorm(gyh, gyl);

        uint64_t pa = f2mul(gxh, gxh);
        uint64_t ea = f2fma(gxh, gxh, f2neg(pa));
        ea = f2fma(f2add(gxh, gxh), gxl, ea);
        uint64_t pb = f2mul(gyh, gyh);
        uint64_t eb = f2fma(gyh, gyh, f2neg(pb));
        eb = f2fma(f2add(gyh, gyh), gyl, eb);
        uint64_t g2h = pa, g2l = ea;
        f2_acc(g2h, g2l, pb, eb);
        f2_renorm(g2h, g2l);
        s_g2[jy][jx] = pk4(g2h, g2l);

        if (jy >= 1 && jy <= TY && jx >= 1 && jx <= TX) {
            // packed |gx|, |gy| (negate both h and l when h-lane negative)
            uint64_t sgx = gxh & 0x8000000080000000ull;
            uint64_t axh = gxh ^ sgx, axl = gxl ^ sgx;
            uint64_t sgy = gyh & 0x8000000080000000ull;
            uint64_t ayh = gyh ^ sgy, ayl = gyl ^ sgy;

            uint64_t m1h, m1l, m2h, m2l;
            df2_mul_const(T1H, T1L, axh, axl, m1h, m1l);
            df2_mul_const(T2H, T2L, axh, axl, m2h, m2l);

            uchar2 bb;
#pragma unroll
            for (int c = 0; c < 2; c++) {
                float AYH, AYL, M1Hf, M1Lf, M2Hf, M2Lf, GXH, GXL, GYH, GYL;
                if (c == 0) {
                    AYH = plo(ayh); AYL = plo(ayl);
                    M1Hf = plo(m1h); M1Lf = plo(m1l);
                    M2Hf = plo(m2h); M2Lf = plo(m2l);
                    GXH = plo(gxh); GXL = plo(gxl);
                    GYH = plo(gyh); GYL = plo(gyl);
                } else {
                    AYH = phi(ayh); AYL = phi(ayl);
                    M1Hf = phi(m1h); M1Lf = phi(m1l);
                    M2Hf = phi(m2h); M2Lf = phi(m2l);
                    GXH = phi(gxh); GXL = phi(gxl);
                    GYH = phi(gyh); GYL = phi(gyl);
                }
                unsigned char bin;
                if (AYH < M1Hf || (AYH == M1Hf && AYL < M1Lf)) bin = 0;       // E/W
                else if (!(AYH < M2Hf || (AYH == M2Hf && AYL < M2Lf))) bin = 2; // N/S
                else {
                    const bool px = (GXH > 0.0f) || (GXH == 0.0f && GXL > 0.0f);
                    const bool py = (GYH > 0.0f) || (GYH == 0.0f && GYL > 0.0f);
                    bin = (px == py) ? 1 : 3;                                  // SW/NE : SE/NW
                }
                if (c == 0) bb.x = bin; else bb.y = bin;
            }
            s_bin[jy][jx] = bb;
        }
    }
    __syncthreads();

    // ---- SE: NMS + sup + block max ----
    const int tx = tid & (TX - 1);
    const int ty = tid >> 5;

    uint64_t c_h, c_l;
    upk4(s_g2[ty + 1][tx + 1], c_h, c_l);
    const uchar2 bin2 = s_bin[ty + 1][tx + 1];

    float sup[2];
#pragma unroll
    for (int comp = 0; comp < 2; comp++) {
        const int bin = comp ? bin2.y : bin2.x;
        int ay, ax_, by, bx_;
        if (bin == 0)      { ay = ty + 1; ax_ = tx + 2; by = ty + 1; bx_ = tx + 0; }
        else if (bin == 2) { ay = ty + 0; ax_ = tx + 1; by = ty + 2; bx_ = tx + 1; }
        else if (bin == 1) { ay = ty + 2; ax_ = tx + 0; by = ty + 0; bx_ = tx + 2; }
        else               { ay = ty + 2; ax_ = tx + 2; by = ty + 0; bx_ = tx + 0; }

        uint64_t nAh, nAl, nBh, nBl;
        upk4(s_g2[ay][ax_], nAh, nAl);
        upk4(s_g2[by][bx_], nBh, nBl);

        float ch, cl, nah, nal, nbh, nbl;
        if (comp == 0) {
            ch = plo(c_h); cl = plo(c_l);
            nah = plo(nAh); nal = plo(nAl);
            nbh = plo(nBh); nbl = plo(nBl);
        } else {
            ch = phi(c_h); cl = phi(c_l);
            nah = phi(nAh); nal = phi(nAl);
            nbh = phi(nBh); nbl = phi(nBl);
        }

        float sv = 0.0f;
        if (dfp_gt(ch, cl, nah, nal) && dfp_gt(ch, cl, nbh, nbl)) {
            float r = sqrtf(ch);
            if (ch > 1.1754944e-38f) {
                float resid = fmaf(-r, r, ch) + cl;
                r = fmaf(resid, 0.5f / r, r);
            }
            sv = r;
        }
        sup[comp] = sv;
    }

    g_sup2[(size_t)p * IMG_HW + (size_t)(y0 + ty) * IMG_W + (x0 + tx)] =
        make_float2(sup[0], sup[1]);

    float vmax = fmaxf(sup[0], sup[1]);
#pragma unroll
    for (int off = 16; off > 0; off >>= 1)
        vmax = fmaxf(vmax, __shfl_xor_sync(0xFFFFFFFF, vmax, off));
    const int wid = tid >> 5;
    if ((tid & 31) == 0) smax[wid] = vmax;
    __syncthreads();
    if (tid == 0) {
        float bmax = smax[0];
#pragma unroll
        for (int i = 1; i < NTHR / 32; i++) bmax = fmaxf(bmax, smax[i]);
        atomicMax(&g_max_bits, __float_as_uint(bmax));
    }
}

// ---------------------------------------------------------------------------
// Fused back: sup -> strong (smem) -> hysteresis conv -> mask; resets g_max
// ---------------------------------------------------------------------------
__global__ __launch_bounds__(NTHR) void fused_back_kernel(float* __restrict__ out) {
    __shared__ float2   s_sup[18][34];
    __shared__ uint64_t s_str[18][34];

    const int x0 = blockIdx.x * TX;
    const int y0 = blockIdx.y * TY;
    const int p  = blockIdx.z;
    const int tid = threadIdx.x;
    const float2* sup_base = g_sup2 + (size_t)p * IMG_HW;

    // min(sup) == 0 exactly (NMS always suppresses some pixels)
    const float mx   = __uint_as_float(g_max_bits);
    const float high = mx * 0.25f;
    const float low  = mx * 0.1f;

    for (int i = tid; i < 18 * 34; i += NTHR) {
        const int yy = i / 34, xx = i - yy * 34;
        const int gx = refl(x0 - 1 + xx, IMG_W);
        const int gy = refl(y0 - 1 + yy, IMG_H);
        const float2 sv = sup_base[gy * IMG_W + gx];
        s_sup[yy][xx] = sv;
        s_str[yy][xx] = pack2(sigm(100.0f * (sv.x - high)),
                              sigm(100.0f * (sv.y - high)));
    }
    __syncthreads();   // also guarantees every thread consumed g_max_bits

    const int tx = tid & (TX - 1);
    const int ty = tid >> 5;

    uint64_t hs = s_str[ty + 0][tx + 0];
    hs = f2add(hs, s_str[ty + 0][tx + 1]);
    hs = f2add(hs, s_str[ty + 0][tx + 2]);
    hs = f2add(hs, s_str[ty + 1][tx + 0]);
    hs = f2add(hs, s_str[ty + 1][tx + 1]);
    hs = f2add(hs, s_str[ty + 1][tx + 2]);
    hs = f2add(hs, s_str[ty + 2][tx + 0]);
    hs = f2add(hs, s_str[ty + 2][tx + 1]);
    hs = f2add(hs, s_str[ty + 2][tx + 2]);

    const uint64_t sc = s_str[ty + 1][tx + 1];
    const float2  sv  = s_sup[ty + 1][tx + 1];

    const float s0 = plo(sc), s1 = phi(sc);
    const float w0 = sigm(100.0f * (sv.x - low)) * (1.0f - s0);
    const float w1 = sigm(100.0f * (sv.y - low)) * (1.0f - s1);
    const float m0 = s0 + w0 * sigm(100.0f * (plo(hs) - 0.5f));
    const float m1 = s1 + w1 * sigm(100.0f * (phi(hs) - 0.5f));

    const size_t idx = (size_t)(y0 + ty) * IMG_W + (x0 + tx);
    out[(size_t)(2 * p)     * IMG_HW + idx] = m0;
    out[(size_t)(2 * p + 1) * IMG_HW + idx] = m1;

    // last-finishing block resets scalars for the next graph replay
    if (tid == 0) {
        const unsigned t = atomicAdd(&g_done, 1u);
        if (t == (unsigned)(NBLOCKS - 1)) {
            g_max_bits = 0u;
            g_done = 0u;
        }
    }
}

// ---------------------------------------------------------------------------
extern "C" void kernel_launch(void* const* d_in, const int* in_sizes, int n_in,
                              void* d_out, int out_size) {
    const float* image = (const float*)d_in[0];
    float* out = (float*)d_out;

    dim3 grd(IMG_W / TX, IMG_H / TY, NPAIR);
    fused_front_kernel<<<grd, NTHR>>>(image);
    fused_back_kernel<<<grd, NTHR>>>(out);
}